// round 4
// baseline (speedup 1.0000x reference)
#include <cuda_runtime.h>

#define N_NODES 120000
#define N_EDGES 1000000
#define DIM 64
#define N_LAYERS 3
#define OUT_STRIDE 256   // (N_LAYERS+1)*DIM
#define NB 8             // nodes per warp

// ---------------- scratch: __device__ globals, accessed directly by symbol ----------------
__device__ int   g_degcol[N_NODES];
__device__ int   g_degrow[N_NODES];
__device__ float g_dinv[N_NODES];
__device__ int   g_rowptr[N_NODES + 1];
__device__ int   g_cursor[N_NODES];
__device__ int2  g_edges[N_EDGES];   // CSR-ordered: {col, __float_as_int(norm)}

// ---------------- setup ----------------
__global__ void init_kernel() {
    int i = blockIdx.x * blockDim.x + threadIdx.x;
    if (i < N_NODES) { g_degcol[i] = 0; g_degrow[i] = 0; }
}

// edge_index is int32 [2, E]: rows at ei[0..E), cols at ei[E..2E)
__global__ void hist_kernel(const int* __restrict__ ei) {
    int e = blockIdx.x * blockDim.x + threadIdx.x;
    if (e >= N_EDGES) return;
    atomicAdd(&g_degrow[ei[e]], 1);
    atomicAdd(&g_degcol[ei[N_EDGES + e]], 1);
}

__global__ void dinv_kernel() {
    int i = blockIdx.x * blockDim.x + threadIdx.x;
    if (i >= N_NODES) return;
    int d = g_degcol[i];
    g_dinv[i] = (d > 0) ? rsqrtf((float)d) : 0.f;
}

// single-block exclusive scan of g_degrow -> g_rowptr, g_cursor
__global__ void scan_kernel() {
    __shared__ int wsum[32];
    __shared__ int stot;
    int tid = threadIdx.x, lane = tid & 31, wid = tid >> 5;
    int carry = 0;
    for (int base = 0; base < N_NODES; base += 1024) {
        int i = base + tid;
        int v = (i < N_NODES) ? g_degrow[i] : 0;
        int x = v;
#pragma unroll
        for (int off = 1; off < 32; off <<= 1) {
            int y = __shfl_up_sync(0xffffffffu, x, off);
            if (lane >= off) x += y;
        }
        if (lane == 31) wsum[wid] = x;
        __syncthreads();
        if (wid == 0) {
            int w = wsum[lane];
#pragma unroll
            for (int off = 1; off < 32; off <<= 1) {
                int y = __shfl_up_sync(0xffffffffu, w, off);
                if (lane >= off) w += y;
            }
            wsum[lane] = w;
            if (lane == 31) stot = w;
        }
        __syncthreads();
        int wprefix = (wid > 0) ? wsum[wid - 1] : 0;
        int excl = carry + wprefix + x - v;
        if (i < N_NODES) { g_rowptr[i] = excl; g_cursor[i] = excl; }
        carry += stot;
        __syncthreads();
    }
    if (tid == 0) g_rowptr[N_NODES] = carry;
}

__global__ void scatter_kernel(const int* __restrict__ ei) {
    int e = blockIdx.x * blockDim.x + threadIdx.x;
    if (e >= N_EDGES) return;
    int r = ei[e];
    int c = ei[N_EDGES + e];
    float nv = g_dinv[r] * g_dinv[c];
    int pos = atomicAdd(&g_cursor[r], 1);
    g_edges[pos] = make_int2(c, __float_as_int(nv));
}

// emb [N,64] -> out[:, 0:64] of [N,256]
__global__ void copy_emb_kernel(const float* __restrict__ emb, float* __restrict__ out) {
    int i = blockIdx.x * blockDim.x + threadIdx.x;  // float4 index over N*16
    if (i >= N_NODES * (DIM / 4)) return;
    int r = i >> 4;
    int q = i & 15;
    ((float4*)out)[(size_t)r * (OUT_STRIDE / 4) + q] = ((const float4*)emb)[i];
}

// ---------------- fused layer: CSR gather + dual GEMV + LeakyReLU ----------------
// 256 threads (8 warps); each warp owns NB=8 nodes. Lane handles dims {2*lane, 2*lane+1}.
// agg2 = xr (.) agg1, so only one accumulator per node is gathered.
// GEMV broadcasts acc components across the warp via shuffles (no atomics, no big smem).
__global__ __launch_bounds__(256) void fused_layer_kernel(
    const float* __restrict__ W1, const float* __restrict__ b1,
    const float* __restrict__ W2, const float* __restrict__ b2,
    float* __restrict__ out, int loff) {
    __shared__ float sW1[DIM * DIM];   // sW1[k*64 + d] = W1[d][k]
    __shared__ float sW2[DIM * DIM];
    __shared__ float sb[DIM];

    int tid = threadIdx.x;
    for (int i = tid; i < DIM * DIM; i += 256) {
        int d = i >> 6, k = i & 63;
        sW1[k * DIM + d] = W1[i];
        sW2[k * DIM + d] = W2[i];
    }
    if (tid < DIM) sb[tid] = b1[tid] + b2[tid];
    __syncthreads();

    int lane = tid & 31;
    int w = tid >> 5;
    int base = (blockIdx.x * 8 + w) * NB;
    const float* x = out + loff;

    float a1x[NB], a1y[NB], a2x[NB], a2y[NB], sv[NB];
#pragma unroll
    for (int j = 0; j < NB; j++) {
        a1x[j] = a1y[j] = a2x[j] = a2y[j] = sv[j] = 0.f;
        int n = base + j;
        if (n < N_NODES) {
            int s0 = g_rowptr[n], s1 = g_rowptr[n + 1];
            float2 xr = *(const float2*)(x + (size_t)n * OUT_STRIDE + 2 * lane);
            for (int e = s0; e < s1; e++) {
                int2 rec = g_edges[e];
                float nv = __int_as_float(rec.y);
                float2 xc = *(const float2*)(x + (size_t)rec.x * OUT_STRIDE + 2 * lane);
                a1x[j] += nv * xc.x;
                a1y[j] += nv * xc.y;
                sv[j] += nv;
            }
            a2x[j] = a1x[j] * xr.x;
            a2y[j] = a1y[j] * xr.y;
        }
    }

    float yx[NB], yy[NB];
    float bx = sb[2 * lane], by = sb[2 * lane + 1];
#pragma unroll
    for (int j = 0; j < NB; j++) { yx[j] = sv[j] * bx; yy[j] = sv[j] * by; }

    // y[d] = sum_k a1[k]*W1[d][k] + a2[k]*W2[d][k]; k = 2*kk (+1): source lane kk, comp x/y
    for (int kk = 0; kk < 32; kk++) {
        float2 w1a = *(const float2*)&sW1[(2 * kk) * DIM + 2 * lane];
        float2 w2a = *(const float2*)&sW2[(2 * kk) * DIM + 2 * lane];
        float2 w1b = *(const float2*)&sW1[(2 * kk + 1) * DIM + 2 * lane];
        float2 w2b = *(const float2*)&sW2[(2 * kk + 1) * DIM + 2 * lane];
#pragma unroll
        for (int j = 0; j < NB; j++) {
            float a1a = __shfl_sync(0xffffffffu, a1x[j], kk);
            float a1b = __shfl_sync(0xffffffffu, a1y[j], kk);
            float a2a = __shfl_sync(0xffffffffu, a2x[j], kk);
            float a2b = __shfl_sync(0xffffffffu, a2y[j], kk);
            yx[j] += a1a * w1a.x + a2a * w2a.x + a1b * w1b.x + a2b * w2b.x;
            yy[j] += a1a * w1a.y + a2a * w2a.y + a1b * w1b.y + a2b * w2b.y;
        }
    }

#pragma unroll
    for (int j = 0; j < NB; j++) {
        int n = base + j;
        if (n < N_NODES) {
            float vx = yx[j], vy = yy[j];
            vx = vx >= 0.f ? vx : 0.2f * vx;
            vy = vy >= 0.f ? vy : 0.2f * vy;
            float* o = out + (size_t)n * OUT_STRIDE + loff + DIM + 2 * lane;
            o[0] = vx;
            o[1] = vy;
        }
    }
}

// ---------------- launch ----------------
extern "C" void kernel_launch(void* const* d_in, const int* in_sizes, int n_in,
                              void* d_out, int out_size) {
    const int* edge_index = (const int*)d_in[0];   // [2,E] int32 (JAX x64 disabled)
    const float* emb = (const float*)d_in[1];      // [N,64]
    const float* W1 = (const float*)d_in[2];       // [3,64,64]
    const float* b1 = (const float*)d_in[3];       // [3,64]
    const float* W2 = (const float*)d_in[4];       // [3,64,64]
    const float* b2 = (const float*)d_in[5];       // [3,64]
    float* out = (float*)d_out;                    // [N,256]

    const int TB = 256;
    const int NBLK = (N_NODES + TB - 1) / TB;
    const int EBLK = (N_EDGES + TB - 1) / TB;

    init_kernel<<<NBLK, TB>>>();
    hist_kernel<<<EBLK, TB>>>(edge_index);
    dinv_kernel<<<NBLK, TB>>>();
    scan_kernel<<<1, 1024>>>();
    scatter_kernel<<<EBLK, TB>>>(edge_index);

    copy_emb_kernel<<<(N_NODES * (DIM / 4) + TB - 1) / TB, TB>>>(emb, out);

    const int FBLK = (N_NODES + 63) / 64;  // 1875
    for (int l = 0; l < N_LAYERS; l++) {
        fused_layer_kernel<<<FBLK, 256>>>(
            W1 + l * DIM * DIM, b1 + l * DIM,
            W2 + l * DIM * DIM, b2 + l * DIM,
            out, l * DIM);
    }
}